// round 12
// baseline (speedup 1.0000x reference)
#include <cuda_runtime.h>
#include <cuda_fp16.h>
#include <cstdint>

#define NN 8192
#define FF 128
#define NEG 0.2f
#define KC 128                 // K-chunk (columns of P per iteration)
#define NCH (NN / KC)          // 64 chunks
#define BROW 272               // smem row pitch bytes (128 halves + 8 pad)

// ----------------------------- device scratch ------------------------------
__device__ float g_xp[(size_t)NN * FF];       // x' = x@W + b (fp32)
__device__ __half g_xht[(size_t)FF * NN];     // x'^T in f16 [f][j]
__device__ float g_ssrc[NN];
__device__ float g_sdst[NN];
__device__ float g_fac[3 * NN];               // ne | ne2 | nb
__device__ unsigned g_maxbits;

__global__ void k_init() { g_maxbits = 0u; }

// ----------------------------- K1: x' = x@W + b ----------------------------
__global__ void k_gemm(const float* __restrict__ x, const float* __restrict__ w,
                       const float* __restrict__ bias) {
    __shared__ float ws[64][128];
    __shared__ float xs[32][64];
    const int tid = threadIdx.x;
    const int row0 = blockIdx.x * 32;
    const int c = tid & 127;
    const int rr = tid >> 7;
    float acc[16];
#pragma unroll
    for (int q = 0; q < 16; ++q) acc[q] = 0.f;
    for (int kb = 0; kb < 128; kb += 64) {
        for (int t = tid; t < 64 * 128; t += 256)
            ws[t >> 7][t & 127] = w[(kb + (t >> 7)) * 128 + (t & 127)];
        for (int t = tid; t < 32 * 64; t += 256)
            xs[t >> 6][t & 63] = x[(size_t)(row0 + (t >> 6)) * 128 + kb + (t & 63)];
        __syncthreads();
#pragma unroll 4
        for (int kk = 0; kk < 64; ++kk) {
            float wv = ws[kk][c];
#pragma unroll
            for (int q = 0; q < 16; ++q) acc[q] += xs[rr * 16 + q][kk] * wv;
        }
        __syncthreads();
    }
    const float b = bias[c];
#pragma unroll
    for (int q = 0; q < 16; ++q)
        g_xp[(size_t)(row0 + rr * 16 + q) * 128 + c] = acc[q] + b;
}

// ----------------------------- K2: scores ----------------------------------
__global__ void k_score(const float* __restrict__ phi) {
    const int warp = threadIdx.x >> 5, lane = threadIdx.x & 31;
    const int i = blockIdx.x * 8 + warp;
    const float4* xr = (const float4*)(g_xp + (size_t)i * FF);
    const float4* pl = (const float4*)phi;
    const float4* ph = (const float4*)(phi + FF);
    float4 xv = xr[lane], a = pl[lane], b = ph[lane];
    float s1 = xv.x * a.x + xv.y * a.y + xv.z * a.z + xv.w * a.w;
    float s2 = xv.x * b.x + xv.y * b.y + xv.z * b.z + xv.w * b.w;
#pragma unroll
    for (int o = 16; o; o >>= 1) {
        s1 += __shfl_xor_sync(0xffffffffu, s1, o);
        s2 += __shfl_xor_sync(0xffffffffu, s2, o);
    }
    if (lane == 0) {
        g_ssrc[i] = s1;
        g_sdst[i] = s2;
        unsigned bits = __float_as_uint(s2);
        unsigned enc = bits ^ ((bits >> 31) ? 0xFFFFFFFFu : 0x80000000u);
        atomicMax(&g_maxbits, enc);
    }
}

// ----------------------------- K2b: per-node factors -----------------------
__global__ void k_factors() {
    const int i = blockIdx.x * 256 + threadIdx.x;
    const unsigned u = g_maxbits;
    const float dmax = __uint_as_float(u ^ ((u >> 31) ? 0x80000000u : 0xFFFFFFFFu));
    const float d = g_sdst[i] - dmax;        // <= 0
    g_fac[i] = expf(d);                      // ne
    g_fac[NN + i] = expf(NEG * d);           // ne2
    g_fac[2 * NN + i] = d;                   // nb
}

// ----------------------------- K2c: X'^T as f16 ----------------------------
__global__ void k_xth() {
    __shared__ float t[32][33];
    const int jb = blockIdx.x * 32, fb = blockIdx.y * 32;
    const int tx = threadIdx.x, ty = threadIdx.y;     // (32,8)
#pragma unroll
    for (int q = 0; q < 4; ++q)
        t[ty + q * 8][tx] = g_xp[(size_t)(jb + ty + q * 8) * 128 + fb + tx];
    __syncthreads();
#pragma unroll
    for (int q = 0; q < 4; ++q)
        g_xht[(size_t)(fb + ty + q * 8) * NN + jb + tx] = __float2half_rn(t[tx][ty + q * 8]);
}

// ----------------------------- K3: HMMA attention --------------------------
// SMEM: [0,96K): factors ne/ne2/nb | P(64 x KC f16, pitch 272) | B(128 x KC f16,
// pitch 272, stored [n][k]) | sdsum[256]
#define FAC_BYTES (3 * NN * 4)                 /* 98304 */
#define P_OFF  FAC_BYTES
#define B_OFF  (P_OFF + 64 * BROW)             /* +17408 */
#define SD_OFF (B_OFF + 128 * BROW)            /* +34816 */
#define SMEM_TOTAL (SD_OFF + 256 * 4)

#define MMA16816(d0, d1, d2, d3, A0, A1, A2, A3, B0, B1)                      \
    asm volatile(                                                             \
        "mma.sync.aligned.m16n8k16.row.col.f32.f16.f16.f32 "                  \
        "{%0,%1,%2,%3}, {%4,%5,%6,%7}, {%8,%9}, {%0,%1,%2,%3};"               \
        : "+f"(d0), "+f"(d1), "+f"(d2), "+f"(d3)                              \
        : "r"(A0), "r"(A1), "r"(A2), "r"(A3), "r"(B0), "r"(B1))

__global__ void __launch_bounds__(256, 1)
k_attn_hmma(const float* __restrict__ adj, float* __restrict__ out) {
    extern __shared__ __align__(16) char smem[];
    float* sne  = (float*)smem;
    float* sne2 = sne + NN;
    float* snb  = sne2 + NN;
    char* Pb = smem + P_OFF;
    char* Bb = smem + B_OFF;
    float* sdsum = (float*)(smem + SD_OFF);

    const int tid = threadIdx.x;
    const int i0 = blockIdx.x * 64;

    // ---- stage all per-node factors into smem (once) ----
    {
        const float4* s = (const float4*)g_fac;
        float4* d = (float4*)smem;
        for (int t = tid; t < 3 * NN / 4; t += 256) d[t] = s[t];
    }

    // ---- producer constants (thread owns row r, column-quarter q) ----
    const int r = tid >> 2, q = tid & 3;
    const int irow = i0 + r;
    const unsigned u = g_maxbits;
    const float dmax = __uint_as_float(u ^ ((u >> 31) ? 0x80000000u : 0xFFFFFFFFu));
    const float ra1 = g_ssrc[irow] + dmax;
    const float mvv = ra1 > 0.f ? ra1 : NEG * ra1;
    const float erow  = expf(ra1 - mvv);
    const float erow2 = expf(NEG * ra1 - mvv);
    float dsum = 0.f;

    // ---- consumer constants (warp owns 16 rows x 64 cols) ----
    const int wid = tid >> 5, lane = tid & 31;
    const int r0 = (wid & 3) * 16, n0 = (wid >> 2) * 64;
    const int gg = lane >> 2, cc = lane & 3;
    float acc[8][4];
#pragma unroll
    for (int nt = 0; nt < 8; ++nt)
#pragma unroll
        for (int k = 0; k < 4; ++k) acc[nt][k] = 0.f;

    const float4* arow4 = (const float4*)(adj + (size_t)irow * NN) + q * 8;
    const uint4* bsrc = (const uint4*)g_xht + (size_t)(tid >> 1) * (NN / 8) + (tid & 1) * 8;
    uint4* bdst = (uint4*)(Bb + (tid >> 1) * BROW + (tid & 1) * 128);
    char* pdst = Pb + r * BROW + q * 64;

    __syncthreads();   // factors visible

    for (int ch = 0; ch < NCH; ++ch) {
        const int j0 = ch * KC;

        // --- B tile: copy f16 X'^T chunk, [n=f][k=j] ---
#pragma unroll
        for (int t2 = 0; t2 < 8; ++t2) bdst[t2] = __ldg(bsrc + ch * 16 + t2);

        // --- P tile: masked leaky-softmax numerators, f16 ---
#pragma unroll
        for (int e = 0; e < 8; ++e) {
            const float4 av = __ldg(arow4 + ch * 32 + e);
            const int j = j0 + q * 32 + e * 4;
            const float4 ne  = *(const float4*)(sne + j);
            const float4 ne2 = *(const float4*)(sne2 + j);
            const float4 nb  = *(const float4*)(snb + j);
            float p0, p1, p2, p3;
            p0 = (ra1 + nb.x) > 0.f ? erow * ne.x : erow2 * ne2.x;
            p1 = (ra1 + nb.y) > 0.f ? erow * ne.y : erow2 * ne2.y;
            p2 = (ra1 + nb.z) > 0.f ? erow * ne.z : erow2 * ne2.z;
            p3 = (ra1 + nb.w) > 0.f ? erow * ne.w : erow2 * ne2.w;
            p0 = (av.x > 0.f || j + 0 == irow) ? p0 : 0.f;
            p1 = (av.y > 0.f || j + 1 == irow) ? p1 : 0.f;
            p2 = (av.z > 0.f || j + 2 == irow) ? p2 : 0.f;
            p3 = (av.w > 0.f || j + 3 == irow) ? p3 : 0.f;
            __half2 h01 = __floats2half2_rn(p0, p1);
            __half2 h23 = __floats2half2_rn(p2, p3);
            const float2 f01 = __half22float2(h01);
            const float2 f23 = __half22float2(h23);
            dsum += (f01.x + f01.y) + (f23.x + f23.y);   // denom == rounded p
            uint2 st;
            st.x = *reinterpret_cast<uint32_t*>(&h01);
            st.y = *reinterpret_cast<uint32_t*>(&h23);
            *(uint2*)(pdst + e * 8) = st;
        }
        __syncthreads();

        // --- mma phase: D += P(64xKC) @ B^T ---
#pragma unroll
        for (int ks = 0; ks < 8; ++ks) {
            const int k0 = ks * 16;
            const char* pa = Pb + (r0 + gg) * BROW + (k0 + 2 * cc) * 2;
            const uint32_t A0 = *(const uint32_t*)(pa);
            const uint32_t A1 = *(const uint32_t*)(pa + 8 * BROW);
            const uint32_t A2 = *(const uint32_t*)(pa + 16);
            const uint32_t A3 = *(const uint32_t*)(pa + 8 * BROW + 16);
#pragma unroll
            for (int nt = 0; nt < 8; ++nt) {
                const char* pb = Bb + (n0 + nt * 8 + gg) * BROW + (k0 + 2 * cc) * 2;
                const uint32_t B0 = *(const uint32_t*)(pb);
                const uint32_t B1 = *(const uint32_t*)(pb + 16);
                MMA16816(acc[nt][0], acc[nt][1], acc[nt][2], acc[nt][3],
                         A0, A1, A2, A3, B0, B1);
            }
        }
        __syncthreads();
    }

    // ---- denominator reduce + epilogue ----
    sdsum[r * 4 + q] = dsum;
    __syncthreads();

    const float* sd = sdsum;
    const int ra = r0 + gg, rb = r0 + gg + 8;
    const float inva = 1.f / (sd[ra * 4] + sd[ra * 4 + 1] + sd[ra * 4 + 2] + sd[ra * 4 + 3]);
    const float invb = 1.f / (sd[rb * 4] + sd[rb * 4 + 1] + sd[rb * 4 + 2] + sd[rb * 4 + 3]);
#pragma unroll
    for (int nt = 0; nt < 8; ++nt) {
        const int col = n0 + nt * 8 + 2 * cc;
        float2 v0 = make_float2(acc[nt][0] * inva, acc[nt][1] * inva);
        float2 v1 = make_float2(acc[nt][2] * invb, acc[nt][3] * invb);
        *(float2*)(out + (size_t)(i0 + ra) * FF + col) = v0;
        *(float2*)(out + (size_t)(i0 + rb) * FF + col) = v1;
    }
}

// ---------------------------------------------------------------------------
extern "C" void kernel_launch(void* const* d_in, const int* in_sizes, int n_in,
                              void* d_out, int out_size) {
    const float* adj  = (const float*)d_in[0];
    const float* x    = (const float*)d_in[1];
    const float* w    = (const float*)d_in[2];
    const float* bias = (const float*)d_in[3];
    const float* phi  = (const float*)d_in[4];
    float* out = (float*)d_out;

    cudaFuncSetAttribute(k_attn_hmma, cudaFuncAttributeMaxDynamicSharedMemorySize,
                         SMEM_TOTAL);

    k_init<<<1, 1>>>();
    k_gemm<<<NN / 32, 256>>>(x, w, bias);
    k_score<<<NN / 8, 256>>>(phi);
    k_factors<<<NN / 256, 256>>>();
    {
        dim3 b(32, 8), g(NN / 32, FF / 32);
        k_xth<<<g, b>>>();
    }
    k_attn_hmma<<<NN / 64, 256, SMEM_TOTAL>>>(adj, out);
}

// round 13
// speedup vs baseline: 1.0617x; 1.0617x over previous
#include <cuda_runtime.h>
#include <cuda_fp16.h>
#include <cstdint>

#define NN 8192
#define FF 128
#define NEG 0.2f
#define KC 128                 // K-chunk (columns of P per iteration)
#define NSPLIT 4
#define NCHS (NN / KC / NSPLIT)   // 16 chunks per split
#define BROW 272               // smem row pitch bytes (128 halves + 8 pad)

// ----------------------------- device scratch ------------------------------
__device__ float g_xp[(size_t)NN * FF];       // x' = x@W + b (fp32)
__device__ __half g_xht[(size_t)FF * NN];     // x'^T in f16 [f][j]
__device__ float g_ssrc[NN];
__device__ float g_sdst[NN];
__device__ float g_fac[3 * NN];               // ne | ne2 | nb (96KB, L2-hot)
__device__ unsigned g_maxbits;
__device__ float g_pnum[(size_t)NSPLIT * NN * FF];  // 16MB split-K partials
__device__ float g_pden[NSPLIT * NN];

__global__ void k_init() { g_maxbits = 0u; }

// ----------------------------- K1: x' = x@W + b ----------------------------
__global__ void k_gemm(const float* __restrict__ x, const float* __restrict__ w,
                       const float* __restrict__ bias) {
    __shared__ float ws[64][128];
    __shared__ float xs[32][64];
    const int tid = threadIdx.x;
    const int row0 = blockIdx.x * 32;
    const int c = tid & 127;
    const int rr = tid >> 7;
    float acc[16];
#pragma unroll
    for (int q = 0; q < 16; ++q) acc[q] = 0.f;
    for (int kb = 0; kb < 128; kb += 64) {
        for (int t = tid; t < 64 * 128; t += 256)
            ws[t >> 7][t & 127] = w[(kb + (t >> 7)) * 128 + (t & 127)];
        for (int t = tid; t < 32 * 64; t += 256)
            xs[t >> 6][t & 63] = x[(size_t)(row0 + (t >> 6)) * 128 + kb + (t & 63)];
        __syncthreads();
#pragma unroll 4
        for (int kk = 0; kk < 64; ++kk) {
            float wv = ws[kk][c];
#pragma unroll
            for (int q = 0; q < 16; ++q) acc[q] += xs[rr * 16 + q][kk] * wv;
        }
        __syncthreads();
    }
    const float b = bias[c];
#pragma unroll
    for (int q = 0; q < 16; ++q)
        g_xp[(size_t)(row0 + rr * 16 + q) * 128 + c] = acc[q] + b;
}

// ----------------------------- K2: scores ----------------------------------
__global__ void k_score(const float* __restrict__ phi) {
    const int warp = threadIdx.x >> 5, lane = threadIdx.x & 31;
    const int i = blockIdx.x * 8 + warp;
    const float4* xr = (const float4*)(g_xp + (size_t)i * FF);
    const float4* pl = (const float4*)phi;
    const float4* ph = (const float4*)(phi + FF);
    float4 xv = xr[lane], a = pl[lane], b = ph[lane];
    float s1 = xv.x * a.x + xv.y * a.y + xv.z * a.z + xv.w * a.w;
    float s2 = xv.x * b.x + xv.y * b.y + xv.z * b.z + xv.w * b.w;
#pragma unroll
    for (int o = 16; o; o >>= 1) {
        s1 += __shfl_xor_sync(0xffffffffu, s1, o);
        s2 += __shfl_xor_sync(0xffffffffu, s2, o);
    }
    if (lane == 0) {
        g_ssrc[i] = s1;
        g_sdst[i] = s2;
        unsigned bits = __float_as_uint(s2);
        unsigned enc = bits ^ ((bits >> 31) ? 0xFFFFFFFFu : 0x80000000u);
        atomicMax(&g_maxbits, enc);
    }
}

// ----------------------------- K2b: per-node factors -----------------------
__global__ void k_factors() {
    const int i = blockIdx.x * 256 + threadIdx.x;
    const unsigned u = g_maxbits;
    const float dmax = __uint_as_float(u ^ ((u >> 31) ? 0x80000000u : 0xFFFFFFFFu));
    const float d = g_sdst[i] - dmax;        // <= 0
    g_fac[i] = expf(d);                      // ne
    g_fac[NN + i] = expf(NEG * d);           // ne2
    g_fac[2 * NN + i] = d;                   // nb
}

// ----------------------------- K2c: X'^T as f16 ----------------------------
__global__ void k_xth() {
    __shared__ float t[32][33];
    const int jb = blockIdx.x * 32, fb = blockIdx.y * 32;
    const int tx = threadIdx.x, ty = threadIdx.y;     // (32,8)
#pragma unroll
    for (int q = 0; q < 4; ++q)
        t[ty + q * 8][tx] = g_xp[(size_t)(jb + ty + q * 8) * 128 + fb + tx];
    __syncthreads();
#pragma unroll
    for (int q = 0; q < 4; ++q)
        g_xht[(size_t)(fb + ty + q * 8) * NN + jb + tx] = __float2half_rn(t[tx][ty + q * 8]);
}

// ----------------------------- K3: HMMA attention (split-K) ----------------
// SMEM: P(64 x KC f16, pitch 272) | B(128 x KC f16, pitch 272) | sdsum[256]
#define P_OFF  0
#define B_OFF  (64 * BROW)                     /* 17408 */
#define SD_OFF (B_OFF + 128 * BROW)            /* 52224 */
#define SMEM_TOTAL (SD_OFF + 256 * 4)          /* 53248 */

#define MMA16816(d0, d1, d2, d3, A0, A1, A2, A3, B0, B1)                      \
    asm volatile(                                                             \
        "mma.sync.aligned.m16n8k16.row.col.f32.f16.f16.f32 "                  \
        "{%0,%1,%2,%3}, {%4,%5,%6,%7}, {%8,%9}, {%0,%1,%2,%3};"               \
        : "+f"(d0), "+f"(d1), "+f"(d2), "+f"(d3)                              \
        : "r"(A0), "r"(A1), "r"(A2), "r"(A3), "r"(B0), "r"(B1))

__global__ void __launch_bounds__(256, 3)
k_attn_hmma(const float* __restrict__ adj) {
    extern __shared__ __align__(16) char smem[];
    char* Pb = smem + P_OFF;
    char* Bb = smem + B_OFF;
    float* sdsum = (float*)(smem + SD_OFF);

    const int tid = threadIdx.x;
    const int i0 = blockIdx.x * 64;
    const int sp = blockIdx.y;                 // K-split id

    const float* sne  = g_fac;
    const float* sne2 = g_fac + NN;
    const float* snb  = g_fac + 2 * NN;

    // ---- producer constants (thread owns row r, column-quarter q) ----
    const int r = tid >> 2, q = tid & 3;
    const int irow = i0 + r;
    const unsigned u = g_maxbits;
    const float dmax = __uint_as_float(u ^ ((u >> 31) ? 0x80000000u : 0xFFFFFFFFu));
    const float ra1 = g_ssrc[irow] + dmax;
    const float mvv = ra1 > 0.f ? ra1 : NEG * ra1;
    const float erow  = expf(ra1 - mvv);
    const float erow2 = expf(NEG * ra1 - mvv);
    float dsum = 0.f;

    // ---- consumer constants (warp owns 16 rows x 64 cols) ----
    const int wid = tid >> 5, lane = tid & 31;
    const int r0 = (wid & 3) * 16, n0 = (wid >> 2) * 64;
    const int gg = lane >> 2, cc = lane & 3;
    float acc[8][4];
#pragma unroll
    for (int nt = 0; nt < 8; ++nt)
#pragma unroll
        for (int k = 0; k < 4; ++k) acc[nt][k] = 0.f;

    const float4* arow4 = (const float4*)(adj + (size_t)irow * NN) + q * 8;
    const uint4* bsrc = (const uint4*)g_xht + (size_t)(tid >> 1) * (NN / 8) + (tid & 1) * 8;
    uint4* bdst = (uint4*)(Bb + (tid >> 1) * BROW + (tid & 1) * 128);
    char* pdst = Pb + r * BROW + q * 64;

    for (int cs = 0; cs < NCHS; ++cs) {
        const int ch = sp * NCHS + cs;
        const int j0 = ch * KC;

        // --- B tile: copy f16 X'^T chunk, [n=f][k=j] ---
#pragma unroll
        for (int t2 = 0; t2 < 8; ++t2) bdst[t2] = __ldg(bsrc + ch * 16 + t2);

        // --- P tile: masked leaky-softmax numerators, f16 ---
#pragma unroll
        for (int e = 0; e < 8; ++e) {
            const float4 av = __ldg(arow4 + ch * 32 + e);
            const int j = j0 + q * 32 + e * 4;
            const float4 ne  = __ldg((const float4*)(sne + j));
            const float4 ne2 = __ldg((const float4*)(sne2 + j));
            const float4 nb  = __ldg((const float4*)(snb + j));
            float p0, p1, p2, p3;
            p0 = (ra1 + nb.x) > 0.f ? erow * ne.x : erow2 * ne2.x;
            p1 = (ra1 + nb.y) > 0.f ? erow * ne.y : erow2 * ne2.y;
            p2 = (ra1 + nb.z) > 0.f ? erow * ne.z : erow2 * ne2.z;
            p3 = (ra1 + nb.w) > 0.f ? erow * ne.w : erow2 * ne2.w;
            p0 = (av.x > 0.f || j + 0 == irow) ? p0 : 0.f;
            p1 = (av.y > 0.f || j + 1 == irow) ? p1 : 0.f;
            p2 = (av.z > 0.f || j + 2 == irow) ? p2 : 0.f;
            p3 = (av.w > 0.f || j + 3 == irow) ? p3 : 0.f;
            __half2 h01 = __floats2half2_rn(p0, p1);
            __half2 h23 = __floats2half2_rn(p2, p3);
            const float2 f01 = __half22float2(h01);
            const float2 f23 = __half22float2(h23);
            dsum += (f01.x + f01.y) + (f23.x + f23.y);   // denom == rounded p
            uint2 st;
            st.x = *reinterpret_cast<uint32_t*>(&h01);
            st.y = *reinterpret_cast<uint32_t*>(&h23);
            *(uint2*)(pdst + e * 8) = st;
        }
        __syncthreads();

        // --- mma phase: D += P(64xKC) @ B^T ---
#pragma unroll
        for (int ks = 0; ks < 8; ++ks) {
            const int k0 = ks * 16;
            const char* pa = Pb + (r0 + gg) * BROW + (k0 + 2 * cc) * 2;
            const uint32_t A0 = *(const uint32_t*)(pa);
            const uint32_t A1 = *(const uint32_t*)(pa + 8 * BROW);
            const uint32_t A2 = *(const uint32_t*)(pa + 16);
            const uint32_t A3 = *(const uint32_t*)(pa + 8 * BROW + 16);
#pragma unroll
            for (int nt = 0; nt < 8; ++nt) {
                const char* pb = Bb + (n0 + nt * 8 + gg) * BROW + (k0 + 2 * cc) * 2;
                const uint32_t B0 = *(const uint32_t*)(pb);
                const uint32_t B1 = *(const uint32_t*)(pb + 16);
                MMA16816(acc[nt][0], acc[nt][1], acc[nt][2], acc[nt][3],
                         A0, A1, A2, A3, B0, B1);
            }
        }
        __syncthreads();
    }

    // ---- denominator partial ----
    sdsum[r * 4 + q] = dsum;
    __syncthreads();
    if (tid < 64)
        g_pden[sp * NN + i0 + tid] = (sdsum[tid * 4] + sdsum[tid * 4 + 1]) +
                                     (sdsum[tid * 4 + 2] + sdsum[tid * 4 + 3]);

    // ---- numerator partial (undivided) ----
    float* pnum = g_pnum + (size_t)sp * NN * FF;
    const int ra = r0 + gg, rb = r0 + gg + 8;
#pragma unroll
    for (int nt = 0; nt < 8; ++nt) {
        const int col = n0 + nt * 8 + 2 * cc;
        *(float2*)(pnum + (size_t)(i0 + ra) * FF + col) = make_float2(acc[nt][0], acc[nt][1]);
        *(float2*)(pnum + (size_t)(i0 + rb) * FF + col) = make_float2(acc[nt][2], acc[nt][3]);
    }
}

// ----------------------------- K4: split-K combine -------------------------
__global__ void k_combine(float* __restrict__ out) {
    const int i = blockIdx.x;
    const int f = threadIdx.x;
    const float den = (g_pden[i] + g_pden[NN + i]) +
                      (g_pden[2 * NN + i] + g_pden[3 * NN + i]);
    const size_t o = (size_t)i * FF + f;
    const float num = (g_pnum[o] + g_pnum[(size_t)NN * FF + o]) +
                      (g_pnum[2 * (size_t)NN * FF + o] + g_pnum[3 * (size_t)NN * FF + o]);
    out[o] = num / den;
}

// ---------------------------------------------------------------------------
extern "C" void kernel_launch(void* const* d_in, const int* in_sizes, int n_in,
                              void* d_out, int out_size) {
    const float* adj  = (const float*)d_in[0];
    const float* x    = (const float*)d_in[1];
    const float* w    = (const float*)d_in[2];
    const float* bias = (const float*)d_in[3];
    const float* phi  = (const float*)d_in[4];
    float* out = (float*)d_out;

    cudaFuncSetAttribute(k_attn_hmma, cudaFuncAttributeMaxDynamicSharedMemorySize,
                         SMEM_TOTAL);

    k_init<<<1, 1>>>();
    k_gemm<<<NN / 32, 256>>>(x, w, bias);
    k_score<<<NN / 8, 256>>>(phi);
    k_factors<<<NN / 256, 256>>>();
    {
        dim3 b(32, 8), g(NN / 32, FF / 32);
        k_xth<<<g, b>>>();
    }
    {
        dim3 g(NN / 64, NSPLIT);
        k_attn_hmma<<<g, 256, SMEM_TOTAL>>>(adj);
    }
    k_combine<<<NN, FF>>>(out);
}

// round 14
// speedup vs baseline: 2.4685x; 2.3251x over previous
#include <cuda_runtime.h>
#include <cuda_fp16.h>
#include <cstdint>

#define NN 8192
#define FF 128
#define NEG 0.2f
#define KC 128                    // K-chunk (columns per iteration)
#define NSPLIT 4
#define NCHS (NN / KC / NSPLIT)   // 16 chunks per split
#define BROW 272                  // smem row pitch bytes (128 halves + 8 pad)

// ----------------------------- device scratch ------------------------------
__device__ float g_xp[(size_t)NN * FF];       // x' = x@W + b (fp32)
__device__ __half g_xht[(size_t)FF * NN];     // x'^T in f16 [f][j]
__device__ float g_ssrc[NN];
__device__ float g_sdst[NN];
__device__ float g_fac[3 * NN];               // ne | ne2 | nb
__device__ unsigned g_maxbits;
__device__ float g_pnum[(size_t)NSPLIT * NN * FF];
__device__ float g_pden[NSPLIT * NN];

// ----------------------------- helpers -------------------------------------
__device__ __forceinline__ uint32_t s2u(const void* p) {
    uint32_t a;
    asm("{ .reg .u64 t; cvta.to.shared.u64 t, %1; cvt.u32.u64 %0, t; }" : "=r"(a) : "l"(p));
    return a;
}
#define LDSM4(d0, d1, d2, d3, addr)                                           \
    asm volatile("ldmatrix.sync.aligned.m8n8.x4.shared.b16 {%0,%1,%2,%3}, [%4];" \
                 : "=r"(d0), "=r"(d1), "=r"(d2), "=r"(d3) : "r"(addr))
#define MMA16816(d0, d1, d2, d3, A0, A1, A2, A3, B0, B1)                      \
    asm volatile(                                                             \
        "mma.sync.aligned.m16n8k16.row.col.f32.f16.f16.f32 "                  \
        "{%0,%1,%2,%3}, {%4,%5,%6,%7}, {%8,%9}, {%0,%1,%2,%3};"               \
        : "+f"(d0), "+f"(d1), "+f"(d2), "+f"(d3)                              \
        : "r"(A0), "r"(A1), "r"(A2), "r"(A3), "r"(B0), "r"(B1))
#define CP16(dst, src)                                                        \
    asm volatile("cp.async.ca.shared.global [%0], [%1], 16;" :: "r"(dst), "l"(src) : "memory")
#define CPCOMMIT() asm volatile("cp.async.commit_group;" ::: "memory")
#define CPWAIT0()  asm volatile("cp.async.wait_group 0;" ::: "memory")

// ----------------------------- K1: x' = x@W + b (+init) --------------------
__global__ void k_gemm(const float* __restrict__ x, const float* __restrict__ w,
                       const float* __restrict__ bias) {
    __shared__ float ws[64][128];
    __shared__ float xs[32][64];
    const int tid = threadIdx.x;
    const int row0 = blockIdx.x * 32;
    if (blockIdx.x == 0 && tid == 0) g_maxbits = 0u;
    const int c = tid & 127;
    const int rr = tid >> 7;
    float acc[16];
#pragma unroll
    for (int q = 0; q < 16; ++q) acc[q] = 0.f;
    for (int kb = 0; kb < 128; kb += 64) {
        for (int t = tid; t < 64 * 128; t += 256)
            ws[t >> 7][t & 127] = w[(kb + (t >> 7)) * 128 + (t & 127)];
        for (int t = tid; t < 32 * 64; t += 256)
            xs[t >> 6][t & 63] = x[(size_t)(row0 + (t >> 6)) * 128 + kb + (t & 63)];
        __syncthreads();
#pragma unroll 4
        for (int kk = 0; kk < 64; ++kk) {
            float wv = ws[kk][c];
#pragma unroll
            for (int q = 0; q < 16; ++q) acc[q] += xs[rr * 16 + q][kk] * wv;
        }
        __syncthreads();
    }
    const float b = bias[c];
#pragma unroll
    for (int q = 0; q < 16; ++q)
        g_xp[(size_t)(row0 + rr * 16 + q) * 128 + c] = acc[q] + b;
}

// ----------------------------- K2: scores ----------------------------------
__global__ void k_score(const float* __restrict__ phi) {
    const int warp = threadIdx.x >> 5, lane = threadIdx.x & 31;
    const int i = blockIdx.x * 8 + warp;
    const float4* xr = (const float4*)(g_xp + (size_t)i * FF);
    const float4* pl = (const float4*)phi;
    const float4* ph = (const float4*)(phi + FF);
    float4 xv = xr[lane], a = pl[lane], b = ph[lane];
    float s1 = xv.x * a.x + xv.y * a.y + xv.z * a.z + xv.w * a.w;
    float s2 = xv.x * b.x + xv.y * b.y + xv.z * b.z + xv.w * b.w;
#pragma unroll
    for (int o = 16; o; o >>= 1) {
        s1 += __shfl_xor_sync(0xffffffffu, s1, o);
        s2 += __shfl_xor_sync(0xffffffffu, s2, o);
    }
    if (lane == 0) {
        g_ssrc[i] = s1;
        g_sdst[i] = s2;
        unsigned bits = __float_as_uint(s2);
        unsigned enc = bits ^ ((bits >> 31) ? 0xFFFFFFFFu : 0x80000000u);
        atomicMax(&g_maxbits, enc);
    }
}

// ----------------------------- K2b: factors + X'^T f16 (merged) ------------
__global__ void k_prep() {
    __shared__ float t[32][33];
    const int jb = blockIdx.x * 32, fb = blockIdx.y * 32;
    const int tx = threadIdx.x, ty = threadIdx.y;     // (32,8)
#pragma unroll
    for (int q = 0; q < 4; ++q)
        t[ty + q * 8][tx] = g_xp[(size_t)(jb + ty + q * 8) * 128 + fb + tx];
    __syncthreads();
#pragma unroll
    for (int q = 0; q < 4; ++q)
        g_xht[(size_t)(fb + ty + q * 8) * NN + jb + tx] = __float2half_rn(t[tx][ty + q * 8]);

    if (blockIdx.y == 0 && blockIdx.x < 32) {
        const int i = blockIdx.x * 256 + ty * 32 + tx;
        const unsigned u = g_maxbits;
        const float dmax = __uint_as_float(u ^ ((u >> 31) ? 0x80000000u : 0xFFFFFFFFu));
        const float d = g_sdst[i] - dmax;     // <= 0
        g_fac[i] = expf(d);
        g_fac[NN + i] = expf(NEG * d);
        g_fac[2 * NN + i] = d;
    }
}

// ----------------------------- K3: HMMA attention (split-K) ----------------
// SMEM: P(64 x 128 f16, pitch 272) | B0 | B1 (128 x 128 f16 each) | row consts
#define P_OFF  0
#define B0_OFF 17408
#define B1_OFF 52224
#define RC_OFF 87040
#define SMEM_TOTAL (RC_OFF + 3 * 64 * 4)

__global__ void __launch_bounds__(256, 2)
k_attn_hmma(const float* __restrict__ adj) {
    extern __shared__ __align__(16) char smem[];
    char* Pb = smem + P_OFF;
    float* sA  = (float*)(smem + RC_OFF);
    float* sE  = sA + 64;
    float* sE2 = sA + 128;

    const int tid = threadIdx.x;
    const int wid = tid >> 5, lane = tid & 31;
    const int i0 = blockIdx.x * 64;
    const int sp = blockIdx.y;
    const int rowbase = i0 + 8 * wid;

    const uint32_t uP = s2u(Pb);
    const uint32_t uB[2] = {s2u(smem + B0_OFF), s2u(smem + B1_OFF)};

    // ---- row constants ----
    if (tid < 64) {
        const int i = i0 + tid;
        const unsigned u = g_maxbits;
        const float dmax = __uint_as_float(u ^ ((u >> 31) ? 0x80000000u : 0xFFFFFFFFu));
        const float ra1 = g_ssrc[i] + dmax;
        const float mvv = ra1 > 0.f ? ra1 : NEG * ra1;
        sA[tid] = ra1;
        sE[tid] = expf(ra1 - mvv);
        sE2[tid] = expf(NEG * ra1 - mvv);
    }

    // ---- consumer fragment addressing ----
    const int r0 = (wid & 3) * 16, n0 = (wid >> 2) * 64;
    const uint32_t aOff = (uint32_t)((r0 + (lane & 15)) * BROW + (lane >> 4) * 16);
    const uint32_t bOff = (uint32_t)((n0 + ((lane >> 4) << 3) + (lane & 7)) * BROW +
                                     ((lane >> 3) & 1) * 16);
    float acc[8][4];
#pragma unroll
    for (int nt = 0; nt < 8; ++nt)
#pragma unroll
        for (int k = 0; k < 4; ++k) acc[nt][k] = 0.f;
    float dacc[8];
#pragma unroll
    for (int rr = 0; rr < 8; ++rr) dacc[rr] = 0.f;

    // ---- B cp.async issue helper (lambda-free macro-ish) ----
    const int bf0 = 16 * wid + (lane >> 4);
    const int bc16 = (lane & 15) * 16;

    // ---- prologue: B(0) + adj/fac prefetch(0) ----
    {
        const int j0 = sp * NCHS * KC;
#pragma unroll
        for (int p = 0; p < 8; ++p) {
            const int f = bf0 + 2 * p;
            CP16(uB[0] + f * BROW + bc16,
                 (const char*)g_xht + ((size_t)f * NN + j0) * 2 + bc16);
        }
        CPCOMMIT();
    }
    float4 av[8], fne, fne2, fnb;
    {
        const int j0 = sp * NCHS * KC;
#pragma unroll
        for (int rr = 0; rr < 8; ++rr)
            av[rr] = __ldg((const float4*)(adj + (size_t)(rowbase + rr) * NN + j0) + lane);
        fne  = __ldg((const float4*)(g_fac + j0) + lane);
        fne2 = __ldg((const float4*)(g_fac + NN + j0) + lane);
        fnb  = __ldg((const float4*)(g_fac + 2 * NN + j0) + lane);
    }
    CPWAIT0();
    __syncthreads();            // row consts + B0 visible

    // ---- build P(0) ----
    {
        const int j0 = sp * NCHS * KC;
        const int jl = j0 + lane * 4;
#pragma unroll
        for (int rr = 0; rr < 8; ++rr) {
            const int irow = rowbase + rr;
            const float ra1 = sA[8 * wid + rr];
            const float er = sE[8 * wid + rr], er2 = sE2[8 * wid + rr];
            float p0 = (ra1 + fnb.x) > 0.f ? er * fne.x : er2 * fne2.x;
            float p1 = (ra1 + fnb.y) > 0.f ? er * fne.y : er2 * fne2.y;
            float p2 = (ra1 + fnb.z) > 0.f ? er * fne.z : er2 * fne2.z;
            float p3 = (ra1 + fnb.w) > 0.f ? er * fne.w : er2 * fne2.w;
            p0 = (av[rr].x > 0.f || jl + 0 == irow) ? p0 : 0.f;
            p1 = (av[rr].y > 0.f || jl + 1 == irow) ? p1 : 0.f;
            p2 = (av[rr].z > 0.f || jl + 2 == irow) ? p2 : 0.f;
            p3 = (av[rr].w > 0.f || jl + 3 == irow) ? p3 : 0.f;
            __half2 h01 = __floats2half2_rn(p0, p1);
            __half2 h23 = __floats2half2_rn(p2, p3);
            const float2 f01 = __half22float2(h01);
            const float2 f23 = __half22float2(h23);
            dacc[rr] += (f01.x + f01.y) + (f23.x + f23.y);
            uint2 st;
            st.x = *reinterpret_cast<uint32_t*>(&h01);
            st.y = *reinterpret_cast<uint32_t*>(&h23);
            *(uint2*)(Pb + (8 * wid + rr) * BROW + lane * 8) = st;
        }
    }
    __syncthreads();            // P0 visible

    // ---- main loop ----
    int buf = 0;
    for (int cs = 0; cs < NCHS; ++cs) {
        const bool more = (cs + 1 < NCHS);
        if (more) {
            const int j0n = (sp * NCHS + cs + 1) * KC;
#pragma unroll
            for (int p = 0; p < 8; ++p) {
                const int f = bf0 + 2 * p;
                CP16(uB[buf ^ 1] + f * BROW + bc16,
                     (const char*)g_xht + ((size_t)f * NN + j0n) * 2 + bc16);
            }
            CPCOMMIT();
#pragma unroll
            for (int rr = 0; rr < 8; ++rr)
                av[rr] = __ldg((const float4*)(adj + (size_t)(rowbase + rr) * NN + j0n) + lane);
            fne  = __ldg((const float4*)(g_fac + j0n) + lane);
            fne2 = __ldg((const float4*)(g_fac + NN + j0n) + lane);
            fnb  = __ldg((const float4*)(g_fac + 2 * NN + j0n) + lane);
        }

        // --- mma on chunk cs ---
        const uint32_t uBc = uB[buf];
#pragma unroll
        for (int ks = 0; ks < 8; ++ks) {
            const uint32_t k2 = ks * 32;      // k0*2 bytes
            uint32_t A0, A1, A2, A3;
            LDSM4(A0, A1, A2, A3, uP + aOff + k2);
#pragma unroll
            for (int p = 0; p < 4; ++p) {
                uint32_t B0, B1, B2, B3;
                LDSM4(B0, B1, B2, B3, uBc + bOff + p * (16 * BROW) + k2);
                MMA16816(acc[2 * p][0], acc[2 * p][1], acc[2 * p][2], acc[2 * p][3],
                         A0, A1, A2, A3, B0, B1);
                MMA16816(acc[2 * p + 1][0], acc[2 * p + 1][1], acc[2 * p + 1][2], acc[2 * p + 1][3],
                         A0, A1, A2, A3, B2, B3);
            }
        }
        CPWAIT0();
        __syncthreads();        // mma done reading P; B(c+1) landed

        if (more) {
            const int j0n = (sp * NCHS + cs + 1) * KC;
            const int jl = j0n + lane * 4;
#pragma unroll
            for (int rr = 0; rr < 8; ++rr) {
                const int irow = rowbase + rr;
                const float ra1 = sA[8 * wid + rr];
                const float er = sE[8 * wid + rr], er2 = sE2[8 * wid + rr];
                float p0 = (ra1 + fnb.x) > 0.f ? er * fne.x : er2 * fne2.x;
                float p1 = (ra1 + fnb.y) > 0.f ? er * fne.y : er2 * fne2.y;
                float p2 = (ra1 + fnb.z) > 0.f ? er * fne.z : er2 * fne2.z;
                float p3 = (ra1 + fnb.w) > 0.f ? er * fne.w : er2 * fne2.w;
                p0 = (av[rr].x > 0.f || jl + 0 == irow) ? p0 : 0.f;
                p1 = (av[rr].y > 0.f || jl + 1 == irow) ? p1 : 0.f;
                p2 = (av[rr].z > 0.f || jl + 2 == irow) ? p2 : 0.f;
                p3 = (av[rr].w > 0.f || jl + 3 == irow) ? p3 : 0.f;
                __half2 h01 = __floats2half2_rn(p0, p1);
                __half2 h23 = __floats2half2_rn(p2, p3);
                const float2 f01 = __half22float2(h01);
                const float2 f23 = __half22float2(h23);
                dacc[rr] += (f01.x + f01.y) + (f23.x + f23.y);
                uint2 st;
                st.x = *reinterpret_cast<uint32_t*>(&h01);
                st.y = *reinterpret_cast<uint32_t*>(&h23);
                *(uint2*)(Pb + (8 * wid + rr) * BROW + lane * 8) = st;
            }
            __syncthreads();    // P(c+1) visible
        }
        buf ^= 1;
    }

    // ---- denominator partials (warp-reduce, fixed order) ----
#pragma unroll
    for (int rr = 0; rr < 8; ++rr) {
        float v = dacc[rr];
#pragma unroll
        for (int o = 16; o; o >>= 1) v += __shfl_xor_sync(0xffffffffu, v, o);
        if (lane == 0) g_pden[sp * NN + rowbase + rr] = v;
    }

    // ---- numerator partials ----
    float* pnum = g_pnum + (size_t)sp * NN * FF;
    const int gg = lane >> 2, cc = lane & 3;
    const int ra = r0 + gg, rb = r0 + gg + 8;
#pragma unroll
    for (int nt = 0; nt < 8; ++nt) {
        const int col = n0 + nt * 8 + 2 * cc;
        *(float2*)(pnum + (size_t)(i0 + ra) * FF + col) = make_float2(acc[nt][0], acc[nt][1]);
        *(float2*)(pnum + (size_t)(i0 + rb) * FF + col) = make_float2(acc[nt][2], acc[nt][3]);
    }
}

// ----------------------------- K4: split-K combine -------------------------
__global__ void k_combine(float* __restrict__ out) {
    const int idx = blockIdx.x * 256 + threadIdx.x;
    const int i = idx >> 7;
    const float den = (g_pden[i] + g_pden[NN + i]) +
                      (g_pden[2 * NN + i] + g_pden[3 * NN + i]);
    const size_t o = (size_t)idx;
    const float num = (g_pnum[o] + g_pnum[(size_t)NN * FF + o]) +
                      (g_pnum[2 * (size_t)NN * FF + o] + g_pnum[3 * (size_t)NN * FF + o]);
    out[o] = num / den;
}

// ---------------------------------------------------------------------------
extern "C" void kernel_launch(void* const* d_in, const int* in_sizes, int n_in,
                              void* d_out, int out_size) {
    const float* adj  = (const float*)d_in[0];
    const float* x    = (const float*)d_in[1];
    const float* w    = (const float*)d_in[2];
    const float* bias = (const float*)d_in[3];
    const float* phi  = (const float*)d_in[4];
    float* out = (float*)d_out;

    cudaFuncSetAttribute(k_attn_hmma, cudaFuncAttributeMaxDynamicSharedMemorySize,
                         SMEM_TOTAL);

    k_gemm<<<NN / 32, 256>>>(x, w, bias);
    k_score<<<NN / 8, 256>>>(phi);
    {
        dim3 b(32, 8), g(NN / 32, FF / 32);
        k_prep<<<g, b>>>();
    }
    {
        dim3 g(NN / 64, NSPLIT);
        k_attn_hmma<<<g, 256, SMEM_TOTAL>>>(adj);
    }
    k_combine<<<NN * FF / 256, 256>>>(out);
}